// round 12
// baseline (speedup 1.0000x reference)
#include <cuda_runtime.h>
#include <math.h>

// ---------------------------------------------------------------------------
// CausalEdgeAttention — algebraically reduced:
//   out = edge_attr + relu(y[src]+y[tgt]) @ Meff + c2
//   y[n]  = 0.5*nf[n]@n_W1 + 0.5*b1      (node precompute, bf16, L2-resident)
//   Meff  = 0.5 * diag(scale) * M,   M = n_W2 @ Wv @ Wo @ Wp
//   c2    = 0.5 * (b2@R2 + bv@R1 + bo@Wp + bp + shift@M)
//   scale = gamma*rsqrt(var+eps), shift = beta - mu*scale (BN stats of h1)
// Edge encoder in the reference is dead code -> skipped.
// stats: tf32 MMA (R8 proven). folds/reduce/final: R8 proven.
// main: bf16 y-gather (z-GEMM eliminated by linearity), f32x2 out-accum.
// ---------------------------------------------------------------------------

#define HDIM 256
#define DDIM 8
#define SGRID 512
#define NMAX 100000

typedef unsigned long long u64;
typedef unsigned int u32;

__device__ __forceinline__ u64 pk(float lo, float hi) {
    u64 r; asm("mov.b64 %0,{%1,%2};" : "=l"(r) : "f"(lo), "f"(hi)); return r;
}
__device__ __forceinline__ void upk(u64 v, float& lo, float& hi) {
    asm("mov.b64 {%0,%1},%2;" : "=f"(lo), "=f"(hi) : "l"(v));
}
__device__ __forceinline__ u64 f2mul(u64 a, u64 b) {
    u64 d; asm("mul.rn.f32x2 %0,%1,%2;" : "=l"(d) : "l"(a), "l"(b)); return d;
}
__device__ __forceinline__ u64 f2fma(u64 a, u64 b, u64 c) {
    u64 d; asm("fma.rn.f32x2 %0,%1,%2,%3;" : "=l"(d) : "l"(a), "l"(b), "l"(c)); return d;
}
__device__ __forceinline__ u32 cvt_tf32(float f) {
    u32 r; asm("cvt.rna.tf32.f32 %0, %1;" : "=r"(r) : "f"(f)); return r;
}
__device__ __forceinline__ u32 badd2(u32 a, u32 b) {
    u32 d; asm("add.rn.bf16x2 %0,%1,%2;" : "=r"(d) : "r"(a), "r"(b)); return d;
}
// pack: low half = lo, high half = hi  (PTX: cvt d, <hi>, <lo>)
__device__ __forceinline__ u32 cvt_bf2(float hi, float lo) {
    u32 d; asm("cvt.rn.bf16x2.f32 %0,%1,%2;" : "=r"(d) : "f"(hi), "f"(lo)); return d;
}

// ------------------------- scratch (device globals; no allocs) -------------
__device__ float  g_R1[HDIM * DDIM];   // Wo @ Wp
__device__ float  g_R2[HDIM * DDIM];   // Wv @ R1
__device__ float  g_M [HDIM * DDIM];   // n_W2 @ R2
__device__ float2 g_ps[SGRID * HDIM];  // BN partials (sum, sumsq)
__device__ float  g_scl[HDIM];         // BN scale per channel
__device__ float  g_shf[HDIM];         // BN shift per channel
__device__ u64    g_Meff[HDIM * 4];    // packed d-pairs: 0.5*scale[h]*M[h][:]
__device__ float  g_c2[DDIM];
__device__ u32    g_y[NMAX * 128];     // y[node][256 ch] as bf16x2, 51.2MB

// ------------------------- pass A: BN statistics via tf32 MMA (R8) ---------
__global__ void __launch_bounds__(256) stats_kernel(const float* __restrict__ nf,
                                                    const int* __restrict__ ei0,
                                                    const int* __restrict__ ei1,
                                                    const float* __restrict__ W1,
                                                    const float* __restrict__ b1,
                                                    int fullE) {
    __shared__ float aS[4][8][32];
    int t = threadIdx.x, w = t >> 5, l = t & 31;
    int g = l >> 2, c = l & 3;

    u32 Bf0[4], Bf1[4];
    float cbl[4], cbh[4];
#pragma unroll
    for (int jj = 0; jj < 4; jj++) {
        int j = 4 * w + jj, n = 8 * j + g;
        Bf0[jj] = cvt_tf32(0.5f * __ldg(W1 + c * HDIM + n));
        Bf1[jj] = cvt_tf32(0.5f * __ldg(W1 + (c + 4) * HDIM + n));
        cbl[jj] = __ldg(b1 + 8 * j + 2 * c);
        cbh[jj] = __ldg(b1 + 8 * j + 2 * c + 1);
    }
    float sL[4] = {0.f, 0.f, 0.f, 0.f}, sH[4] = {0.f, 0.f, 0.f, 0.f};
    float qL[4] = {0.f, 0.f, 0.f, 0.f}, qH[4] = {0.f, 0.f, 0.f, 0.f};
    const float4* nfp = (const float4*)nf;

    for (int base = blockIdx.x * 128; base < fullE; base += SGRID * 128) {
        __syncthreads();
        if (t < 128) {
            int e = base + t;
            if (e < fullE) {
                int r = t & 15, tt = t >> 4;
                int si = __ldg(ei0 + e), ti = __ldg(ei1 + e);
                float4 s0 = __ldg(nfp + 2 * si), s1 = __ldg(nfp + 2 * si + 1);
                float4 u0 = __ldg(nfp + 2 * ti), u1 = __ldg(nfp + 2 * ti + 1);
                float v[8];
                v[0] = s0.x + u0.x; v[1] = s0.y + u0.y;
                v[2] = s0.z + u0.z; v[3] = s0.w + u0.w;
                v[4] = s1.x + u1.x; v[5] = s1.y + u1.y;
                v[6] = s1.z + u1.z; v[7] = s1.w + u1.w;
                int rr = r & 7, hi = r >> 3;
#pragma unroll
                for (int cc = 0; cc < 4; cc++) {
                    aS[hi][tt][rr * 4 + cc]     = __uint_as_float(cvt_tf32(v[cc]));
                    aS[2 + hi][tt][rr * 4 + cc] = __uint_as_float(cvt_tf32(v[cc + 4]));
                }
            }
        }
        __syncthreads();
#pragma unroll
        for (int tt = 0; tt < 8; tt++) {
            if (base + 16 * tt >= fullE) break;
            u32 A0 = __float_as_uint(aS[0][tt][l]);
            u32 A1 = __float_as_uint(aS[1][tt][l]);
            u32 A2 = __float_as_uint(aS[2][tt][l]);
            u32 A3 = __float_as_uint(aS[3][tt][l]);
#pragma unroll
            for (int jj = 0; jj < 4; jj++) {
                float d0, d1, d2, d3;
                asm volatile(
                    "mma.sync.aligned.m16n8k8.row.col.f32.tf32.tf32.f32 "
                    "{%0,%1,%2,%3}, {%4,%5,%6,%7}, {%8,%9}, {%10,%11,%12,%13};\n"
                    : "=f"(d0), "=f"(d1), "=f"(d2), "=f"(d3)
                    : "r"(A0), "r"(A1), "r"(A2), "r"(A3),
                      "r"(Bf0[jj]), "r"(Bf1[jj]),
                      "f"(cbl[jj]), "f"(cbh[jj]), "f"(cbl[jj]), "f"(cbh[jj]));
                float r0 = fmaxf(d0, 0.f), r1 = fmaxf(d1, 0.f);
                float r2 = fmaxf(d2, 0.f), r3 = fmaxf(d3, 0.f);
                sL[jj] += r0 + r2;
                sH[jj] += r1 + r3;
                qL[jj] = fmaf(r0, r0, qL[jj]); qL[jj] = fmaf(r2, r2, qL[jj]);
                qH[jj] = fmaf(r1, r1, qH[jj]); qH[jj] = fmaf(r3, r3, qH[jj]);
            }
        }
    }
#pragma unroll
    for (int jj = 0; jj < 4; jj++)
#pragma unroll
        for (int off = 4; off <= 16; off <<= 1) {
            sL[jj] += __shfl_xor_sync(0xffffffffu, sL[jj], off);
            sH[jj] += __shfl_xor_sync(0xffffffffu, sH[jj], off);
            qL[jj] += __shfl_xor_sync(0xffffffffu, qL[jj], off);
            qH[jj] += __shfl_xor_sync(0xffffffffu, qH[jj], off);
        }
    if (g == 0) {
#pragma unroll
        for (int jj = 0; jj < 4; jj++) {
            int ch = 8 * (4 * w + jj) + 2 * c;
            g_ps[blockIdx.x * HDIM + ch]     = make_float2(sL[jj], qL[jj]);
            g_ps[blockIdx.x * HDIM + ch + 1] = make_float2(sH[jj], qH[jj]);
        }
    }
}

// ------------------------- node precompute: y = 0.5*nf@W1 + 0.5*b1 (bf16) --
__global__ void __launch_bounds__(256) ypre_kernel(const float* __restrict__ nf,
                                                   const float* __restrict__ W1,
                                                   const float* __restrict__ b1,
                                                   int N) {
    __shared__ u64 wp[HDIM * 4];
    __shared__ float b1h[HDIM];
    int t = threadIdx.x;
    for (int idx = t; idx < HDIM * 4; idx += 256) {
        int h = idx >> 2, p = idx & 3;
        wp[idx] = pk(0.5f * W1[(2 * p) * HDIM + h], 0.5f * W1[(2 * p + 1) * HDIM + h]);
    }
    b1h[t] = 0.5f * b1[t];
    __syncthreads();

    int base = (blockIdx.x * 256 + t) * 2;
    if (base >= N) return;
    int n0 = base, n1 = min(base + 1, N - 1);
    const float4* nfp = (const float4*)nf;
    float4 a0 = __ldg(nfp + 2 * n0), a1 = __ldg(nfp + 2 * n0 + 1);
    float4 c0 = __ldg(nfp + 2 * n1), c1 = __ldg(nfp + 2 * n1 + 1);
    u64 nA[4] = {pk(a0.x, a0.y), pk(a0.z, a0.w), pk(a1.x, a1.y), pk(a1.z, a1.w)};
    u64 nB[4] = {pk(c0.x, c0.y), pk(c0.z, c0.w), pk(c1.x, c1.y), pk(c1.z, c1.w)};
    u32* y0 = g_y + n0 * 128;
    u32* y1 = g_y + n1 * 128;
    bool w1v = (base + 1) < N;

#pragma unroll 2
    for (int ch = 0; ch < 32; ch++) {
        u32 oA[4], oB[4];
#pragma unroll
        for (int pp = 0; pp < 4; pp++) {
            int h = ch * 8 + 2 * pp;
            u64 w0a = wp[h * 4 + 0], w1a = wp[h * 4 + 1];
            u64 w2a = wp[h * 4 + 2], w3a = wp[h * 4 + 3];
            u64 w0b = wp[(h + 1) * 4 + 0], w1b = wp[(h + 1) * 4 + 1];
            u64 w2b = wp[(h + 1) * 4 + 2], w3b = wp[(h + 1) * 4 + 3];
            float bA = b1h[h], bB = b1h[h + 1];
            u64 s;
            float lo, hi;
            s = f2mul(nA[0], w0a); s = f2fma(nA[1], w1a, s);
            s = f2fma(nA[2], w2a, s); s = f2fma(nA[3], w3a, s);
            upk(s, lo, hi); float yA0 = lo + hi + bA;
            s = f2mul(nA[0], w0b); s = f2fma(nA[1], w1b, s);
            s = f2fma(nA[2], w2b, s); s = f2fma(nA[3], w3b, s);
            upk(s, lo, hi); float yA1 = lo + hi + bB;
            oA[pp] = cvt_bf2(yA1, yA0);
            s = f2mul(nB[0], w0a); s = f2fma(nB[1], w1a, s);
            s = f2fma(nB[2], w2a, s); s = f2fma(nB[3], w3a, s);
            upk(s, lo, hi); float yB0 = lo + hi + bA;
            s = f2mul(nB[0], w0b); s = f2fma(nB[1], w1b, s);
            s = f2fma(nB[2], w2b, s); s = f2fma(nB[3], w3b, s);
            upk(s, lo, hi); float yB1 = lo + hi + bB;
            oB[pp] = cvt_bf2(yB1, yB0);
        }
        *(uint4*)(y0 + ch * 4) = make_uint4(oA[0], oA[1], oA[2], oA[3]);
        if (w1v) *(uint4*)(y1 + ch * 4) = make_uint4(oB[0], oB[1], oB[2], oB[3]);
    }
}

// ------------------------- fold: Out[H,8] = A[H,H] @ B[H,8] (R8 proven) ----
__global__ void __launch_bounds__(256) fold_kernel(const float* __restrict__ A,
                                                   const float* __restrict__ Bext,
                                                   int mode) {
    __shared__ u64 Bs[HDIM * 4];
    const u64* Bv = (mode == 0) ? (const u64*)Bext
                   : (mode == 1) ? (const u64*)g_R1 : (const u64*)g_R2;
    float* Out = (mode == 0) ? g_R1 : (mode == 1) ? g_R2 : g_M;
    int t = threadIdx.x;
    for (int i = t; i < HDIM * 4; i += 256) Bs[i] = Bv[i];
    __syncthreads();

    int h = blockIdx.x * 8 + (t >> 5);
    int lane = t & 31;
    const float* Ar = A + h * HDIM;
    u64 a0 = 0, a1 = 0, a2 = 0, a3 = 0;
#pragma unroll
    for (int i = 0; i < 8; i++) {
        int k = lane + 32 * i;
        float a = __ldg(Ar + k);
        u64 aa = pk(a, a);
        a0 = f2fma(aa, Bs[k * 4 + 0], a0);
        a1 = f2fma(aa, Bs[k * 4 + 1], a1);
        a2 = f2fma(aa, Bs[k * 4 + 2], a2);
        a3 = f2fma(aa, Bs[k * 4 + 3], a3);
    }
    float r[8];
    upk(a0, r[0], r[1]); upk(a1, r[2], r[3]);
    upk(a2, r[4], r[5]); upk(a3, r[6], r[7]);
#pragma unroll
    for (int off = 16; off; off >>= 1)
#pragma unroll
        for (int d = 0; d < 8; d++) r[d] += __shfl_xor_sync(0xffffffffu, r[d], off);
    if (lane == 0) {
        float4* o = (float4*)(Out + h * 8);
        o[0] = make_float4(r[0], r[1], r[2], r[3]);
        o[1] = make_float4(r[4], r[5], r[6], r[7]);
    }
}

// ------------------------- BN reduce: one block per channel (R8) -----------
__global__ void __launch_bounds__(256) reduce_kernel(const float* __restrict__ gamma,
                                                     const float* __restrict__ beta,
                                                     const float* __restrict__ nf,
                                                     const int* __restrict__ ei0,
                                                     const int* __restrict__ ei1,
                                                     const float* __restrict__ W1,
                                                     const float* __restrict__ b1,
                                                     int fullE, int E) {
    __shared__ float ss[8], qq[8];
    int h = blockIdx.x, t = threadIdx.x;
    float2 p0 = g_ps[t * HDIM + h];
    float2 p1 = g_ps[(t + 256) * HDIM + h];
    float s = p0.x + p1.x, q = p0.y + p1.y;
#pragma unroll
    for (int off = 16; off; off >>= 1) {
        s += __shfl_xor_sync(0xffffffffu, s, off);
        q += __shfl_xor_sync(0xffffffffu, q, off);
    }
    if ((t & 31) == 0) { ss[t >> 5] = s; qq[t >> 5] = q; }
    __syncthreads();
    if (t == 0) {
        s = 0.f; q = 0.f;
#pragma unroll
        for (int i = 0; i < 8; i++) { s += ss[i]; q += qq[i]; }
        for (int e = fullE; e < E; e++) {
            int si = __ldg(ei0 + e), ti = __ldg(ei1 + e);
            float z = __ldg(b1 + h);
#pragma unroll
            for (int k = 0; k < 8; k++)
                z = fmaf(0.5f * (__ldg(nf + si * 8 + k) + __ldg(nf + ti * 8 + k)),
                         __ldg(W1 + k * HDIM + h), z);
            float hv = fmaxf(z, 0.f);
            s += hv; q = fmaf(hv, hv, q);
        }
        float invE = 1.0f / (float)E;
        float mu = s * invE;
        float var = fmaxf(q * invE - mu * mu, 0.f);
        float scl = gamma[h] * rsqrtf(var + 1e-5f);
        g_scl[h] = scl;
        g_shf[h] = beta[h] - mu * scl;
    }
}

// ------------------------- final: pack Meff + compute c2 (R8) --------------
__global__ void __launch_bounds__(256) final_kernel(const float* __restrict__ b2,
                                                    const float* __restrict__ bv,
                                                    const float* __restrict__ bo,
                                                    const float* __restrict__ bp,
                                                    const float* __restrict__ Wp) {
    int t = threadIdx.x;
    float scl = g_scl[t];
#pragma unroll
    for (int p = 0; p < 4; p++)
        g_Meff[t * 4 + p] = pk(0.5f * scl * g_M[t * 8 + 2 * p],
                               0.5f * scl * g_M[t * 8 + 2 * p + 1]);

    int w = t >> 5, lane = t & 31;
    if (w < DDIM) {
        float r = 0.f;
#pragma unroll
        for (int i = 0; i < 8; i++) {
            int h = lane + 32 * i;
            r += g_shf[h] * g_M[h * 8 + w] + __ldg(b2 + h) * g_R2[h * 8 + w]
               + __ldg(bv + h) * g_R1[h * 8 + w] + __ldg(bo + h) * __ldg(Wp + h * 8 + w);
        }
#pragma unroll
        for (int off = 16; off; off >>= 1) r += __shfl_xor_sync(0xffffffffu, r, off);
        if (lane == 0) g_c2[w] = 0.5f * (__ldg(bp + w) + r);
    }
}

// ------------------------- pass B: main via bf16 y-gather ------------------
__global__ void __launch_bounds__(256, 2) main_kernel(const float* __restrict__ edge_attr,
                                                      const int* __restrict__ ei0,
                                                      const int* __restrict__ ei1,
                                                      float* __restrict__ out,
                                                      int E) {
    __shared__ u64 mp[HDIM * 4];
    int t = threadIdx.x;
    for (int idx = t; idx < HDIM * 4; idx += 256) mp[idx] = g_Meff[idx];
    __syncthreads();

    int base = (blockIdx.x * 256 + t) * 4;
    if (base >= E) return;

    const u32* ys[4];
    const u32* yt[4];
#pragma unroll
    for (int i = 0; i < 4; i++) {
        int e = min(base + i, E - 1);
        ys[i] = g_y + __ldg(ei0 + e) * 128;
        yt[i] = g_y + __ldg(ei1 + e) * 128;
    }

    u64 acc[4][4];
#pragma unroll
    for (int i = 0; i < 4; i++)
#pragma unroll
        for (int p = 0; p < 4; p++) acc[i][p] = 0;

#pragma unroll 2
    for (int ch = 0; ch < 32; ch++) {
        u32 zp[4][4];
#pragma unroll
        for (int i = 0; i < 4; i++) {
            uint4 a = __ldg((const uint4*)(ys[i] + ch * 4));
            uint4 b = __ldg((const uint4*)(yt[i] + ch * 4));
            zp[i][0] = badd2(a.x, b.x);
            zp[i][1] = badd2(a.y, b.y);
            zp[i][2] = badd2(a.z, b.z);
            zp[i][3] = badd2(a.w, b.w);
        }
#pragma unroll
        for (int pp = 0; pp < 4; pp++) {
            int h = ch * 8 + 2 * pp;
            u64 m0 = mp[h * 4 + 0], m1 = mp[h * 4 + 1];
            u64 m2 = mp[h * 4 + 2], m3 = mp[h * 4 + 3];
            u64 m4 = mp[(h + 1) * 4 + 0], m5 = mp[(h + 1) * 4 + 1];
            u64 m6 = mp[(h + 1) * 4 + 2], m7 = mp[(h + 1) * 4 + 3];
#pragma unroll
            for (int i = 0; i < 4; i++) {
                u32 v = zp[i][pp];
                float z0 = fmaxf(__uint_as_float(v << 16), 0.f);          // even h
                float z1 = fmaxf(__uint_as_float(v & 0xFFFF0000u), 0.f);  // odd h
                u64 h0 = pk(z0, z0), h1 = pk(z1, z1);
                acc[i][0] = f2fma(h0, m0, acc[i][0]);
                acc[i][1] = f2fma(h0, m1, acc[i][1]);
                acc[i][2] = f2fma(h0, m2, acc[i][2]);
                acc[i][3] = f2fma(h0, m3, acc[i][3]);
                acc[i][0] = f2fma(h1, m4, acc[i][0]);
                acc[i][1] = f2fma(h1, m5, acc[i][1]);
                acc[i][2] = f2fma(h1, m6, acc[i][2]);
                acc[i][3] = f2fma(h1, m7, acc[i][3]);
            }
        }
    }

    float cz[8];
#pragma unroll
    for (int d = 0; d < 8; d++) cz[d] = g_c2[d];

    const float4* eap = (const float4*)edge_attr;
    float4* outp = (float4*)out;
#pragma unroll
    for (int i = 0; i < 4; i++) {
        int e = base + i;
        if (e >= E) break;
        float4 e0 = __ldg(eap + e * 2), e1 = __ldg(eap + e * 2 + 1);
        float x0, x1, x2, x3, x4, x5, x6, x7;
        upk(acc[i][0], x0, x1); upk(acc[i][1], x2, x3);
        upk(acc[i][2], x4, x5); upk(acc[i][3], x6, x7);
        float4 o0, o1;
        o0.x = e0.x + x0 + cz[0]; o0.y = e0.y + x1 + cz[1];
        o0.z = e0.z + x2 + cz[2]; o0.w = e0.w + x3 + cz[3];
        o1.x = e1.x + x4 + cz[4]; o1.y = e1.y + x5 + cz[5];
        o1.z = e1.z + x6 + cz[6]; o1.w = e1.w + x7 + cz[7];
        outp[e * 2] = o0; outp[e * 2 + 1] = o1;
    }
}

// ------------------------- launch ------------------------------------------
extern "C" void kernel_launch(void* const* d_in, const int* in_sizes, int n_in,
                              void* d_out, int out_size) {
    const float* edge_attr = (const float*)d_in[0];
    const float* nf        = (const float*)d_in[1];
    const int*   ei        = (const int*)  d_in[2];
    // d_in[3..8] = edge encoder params: dead code in the reference, unused.
    const float* nW1   = (const float*)d_in[9];
    const float* nb1   = (const float*)d_in[10];
    const float* ngam  = (const float*)d_in[11];
    const float* nbet  = (const float*)d_in[12];
    const float* nW2   = (const float*)d_in[13];
    const float* nb2   = (const float*)d_in[14];
    const float* Wv    = (const float*)d_in[15];
    const float* bv    = (const float*)d_in[16];
    const float* Wo    = (const float*)d_in[17];
    const float* bo    = (const float*)d_in[18];
    const float* Wp    = (const float*)d_in[19];
    const float* bp    = (const float*)d_in[20];
    (void)n_in; (void)out_size;

    int E = in_sizes[0] / DDIM;
    int N = in_sizes[1] / DDIM;
    if (N > NMAX) N = NMAX;
    const int* ei0 = ei;
    const int* ei1 = ei + E;
    float* out = (float*)d_out;
    int fullE = (E / 16) * 16;

    // BN statistics via tensor cores (longest chain starts immediately)
    stats_kernel<<<SGRID, 256>>>(nf, ei0, ei1, nW1, nb1, fullE);

    // node y precompute (bf16), 2 nodes/thread
    int gridY = (N + 511) / 512;
    ypre_kernel<<<gridY, 256>>>(nf, nW1, nb1, N);

    // weight folding (grid-parallel, R8 proven)
    fold_kernel<<<32, 256>>>(Wo, Wp, 0);    // R1 = Wo @ Wp
    fold_kernel<<<32, 256>>>(Wv, Wp, 1);    // R2 = Wv @ R1
    fold_kernel<<<32, 256>>>(nW2, Wp, 2);   // M  = nW2 @ R2

    // BN finalize
    reduce_kernel<<<HDIM, 256>>>(ngam, nbet, nf, ei0, ei1, nW1, nb1, fullE, E);
    final_kernel<<<1, 256>>>(nb2, bv, bo, bp, Wp);

    // main fused pass via y-gather, 4 edges / thread
    int gridB = (E + 1023) / 1024;
    main_kernel<<<gridB, 256>>>(edge_attr, ei0, ei1, out, E);
}

// round 13
// speedup vs baseline: 1.7007x; 1.7007x over previous
#include <cuda_runtime.h>
#include <math.h>

// ---------------------------------------------------------------------------
// CausalEdgeAttention — algebraically reduced:
//   out = edge_attr + relu(nc@W1eff + b1) @ Meff + c2
//   M = nW2@Wv@Wo@Wp  reassociated as  M = X@Y,  X = nW2@Wv,  Y = Wo@Wp
//   u = b2@Wv  (so b2@R2 == u@Y);  c2 = 0.5*(bp + Σ_h v[h]),
//   v[h,:] = shift[h]*M[h,:] + (u[h]+bv[h])*Y[h,:] + bo[h]*Wp[h,:]
// Edge encoder in the reference is dead code -> skipped.
// mega kernel: stats blocks (tf32 MMA, R8 proven) + independent X/Y/u blocks
// riding the tail wave. reduce: per-channel BN finalize + M/Meff/v row.
// final: c2 sum only. main: byte-identical R8 scalar f32x2 (proven ~95us).
// ---------------------------------------------------------------------------

#define HDIM 256
#define DDIM 8
#define SGRID 512

typedef unsigned long long u64;
typedef unsigned int u32;

__device__ __forceinline__ u64 pk(float lo, float hi) {
    u64 r; asm("mov.b64 %0,{%1,%2};" : "=l"(r) : "f"(lo), "f"(hi)); return r;
}
__device__ __forceinline__ void upk(u64 v, float& lo, float& hi) {
    asm("mov.b64 {%0,%1},%2;" : "=f"(lo), "=f"(hi) : "l"(v));
}
__device__ __forceinline__ u64 f2mul(u64 a, u64 b) {
    u64 d; asm("mul.rn.f32x2 %0,%1,%2;" : "=l"(d) : "l"(a), "l"(b)); return d;
}
__device__ __forceinline__ u64 f2fma(u64 a, u64 b, u64 c) {
    u64 d; asm("fma.rn.f32x2 %0,%1,%2,%3;" : "=l"(d) : "l"(a), "l"(b), "l"(c)); return d;
}
__device__ __forceinline__ u32 cvt_tf32(float f) {
    u32 r; asm("cvt.rna.tf32.f32 %0, %1;" : "=r"(r) : "f"(f)); return r;
}

// ------------------------- scratch (device globals; no allocs) -------------
__device__ float  g_X[HDIM * HDIM];    // nW2 @ Wv
__device__ float  g_Y[HDIM * DDIM];    // Wo @ Wp
__device__ float  g_u[HDIM];           // b2 @ Wv
__device__ float  g_v[HDIM * DDIM];    // per-h c2 contributions
__device__ float2 g_ps[SGRID * HDIM];  // BN partials (sum, sumsq)
__device__ u64    g_Meff[HDIM * 4];    // packed d-pairs: 0.5*scale[h]*M[h][:]
__device__ float  g_c2[DDIM];

// ------------------------- mega: stats (tf32 MMA) + X + Y + u --------------
__global__ void __launch_bounds__(256) mega_kernel(const float* __restrict__ nf,
                                                   const int* __restrict__ ei0,
                                                   const int* __restrict__ ei1,
                                                   const float* __restrict__ W1,
                                                   const float* __restrict__ b1,
                                                   const float* __restrict__ Wo,
                                                   const float* __restrict__ Wv,
                                                   const float* __restrict__ nW2,
                                                   const float* __restrict__ Wp,
                                                   const float* __restrict__ b2,
                                                   int fullE) {
    __shared__ float aS[4][8][32];     // stats A-frags (4KB)
    __shared__ float rows[8][256];     // X: staged nW2 rows (8KB)
    __shared__ u64   Bs[HDIM * 4];     // Y: staged Wp pairs (8KB)
    int bid = blockIdx.x;
    int t = threadIdx.x, w = t >> 5, l = t & 31;

    if (bid < SGRID) {
        // ---------------- BN statistics via tf32 MMA (R8 proven) ----------
        int g = l >> 2, c = l & 3;
        u32 Bf0[4], Bf1[4];
        float cbl[4], cbh[4];
#pragma unroll
        for (int jj = 0; jj < 4; jj++) {
            int j = 4 * w + jj, n = 8 * j + g;
            Bf0[jj] = cvt_tf32(0.5f * __ldg(W1 + c * HDIM + n));
            Bf1[jj] = cvt_tf32(0.5f * __ldg(W1 + (c + 4) * HDIM + n));
            cbl[jj] = __ldg(b1 + 8 * j + 2 * c);
            cbh[jj] = __ldg(b1 + 8 * j + 2 * c + 1);
        }
        float sL[4] = {0.f, 0.f, 0.f, 0.f}, sH[4] = {0.f, 0.f, 0.f, 0.f};
        float qL[4] = {0.f, 0.f, 0.f, 0.f}, qH[4] = {0.f, 0.f, 0.f, 0.f};
        const float4* nfp = (const float4*)nf;

        for (int base = bid * 128; base < fullE; base += SGRID * 128) {
            __syncthreads();
            if (t < 128) {
                int e = base + t;
                if (e < fullE) {
                    int r = t & 15, tt = t >> 4;
                    int si = __ldg(ei0 + e), ti = __ldg(ei1 + e);
                    float4 s0 = __ldg(nfp + 2 * si), s1 = __ldg(nfp + 2 * si + 1);
                    float4 u0 = __ldg(nfp + 2 * ti), u1 = __ldg(nfp + 2 * ti + 1);
                    float v[8];
                    v[0] = s0.x + u0.x; v[1] = s0.y + u0.y;
                    v[2] = s0.z + u0.z; v[3] = s0.w + u0.w;
                    v[4] = s1.x + u1.x; v[5] = s1.y + u1.y;
                    v[6] = s1.z + u1.z; v[7] = s1.w + u1.w;
                    int rr = r & 7, hi = r >> 3;
#pragma unroll
                    for (int cc = 0; cc < 4; cc++) {
                        aS[hi][tt][rr * 4 + cc]     = __uint_as_float(cvt_tf32(v[cc]));
                        aS[2 + hi][tt][rr * 4 + cc] = __uint_as_float(cvt_tf32(v[cc + 4]));
                    }
                }
            }
            __syncthreads();
#pragma unroll
            for (int tt = 0; tt < 8; tt++) {
                if (base + 16 * tt >= fullE) break;
                u32 A0 = __float_as_uint(aS[0][tt][l]);
                u32 A1 = __float_as_uint(aS[1][tt][l]);
                u32 A2 = __float_as_uint(aS[2][tt][l]);
                u32 A3 = __float_as_uint(aS[3][tt][l]);
#pragma unroll
                for (int jj = 0; jj < 4; jj++) {
                    float d0, d1, d2, d3;
                    asm volatile(
                        "mma.sync.aligned.m16n8k8.row.col.f32.tf32.tf32.f32 "
                        "{%0,%1,%2,%3}, {%4,%5,%6,%7}, {%8,%9}, {%10,%11,%12,%13};\n"
                        : "=f"(d0), "=f"(d1), "=f"(d2), "=f"(d3)
                        : "r"(A0), "r"(A1), "r"(A2), "r"(A3),
                          "r"(Bf0[jj]), "r"(Bf1[jj]),
                          "f"(cbl[jj]), "f"(cbh[jj]), "f"(cbl[jj]), "f"(cbh[jj]));
                    float r0 = fmaxf(d0, 0.f), r1 = fmaxf(d1, 0.f);
                    float r2 = fmaxf(d2, 0.f), r3 = fmaxf(d3, 0.f);
                    sL[jj] += r0 + r2;
                    sH[jj] += r1 + r3;
                    qL[jj] = fmaf(r0, r0, qL[jj]); qL[jj] = fmaf(r2, r2, qL[jj]);
                    qH[jj] = fmaf(r1, r1, qH[jj]); qH[jj] = fmaf(r3, r3, qH[jj]);
                }
            }
        }
#pragma unroll
        for (int jj = 0; jj < 4; jj++)
#pragma unroll
            for (int off = 4; off <= 16; off <<= 1) {
                sL[jj] += __shfl_xor_sync(0xffffffffu, sL[jj], off);
                sH[jj] += __shfl_xor_sync(0xffffffffu, sH[jj], off);
                qL[jj] += __shfl_xor_sync(0xffffffffu, qL[jj], off);
                qH[jj] += __shfl_xor_sync(0xffffffffu, qH[jj], off);
            }
        if (g == 0) {
#pragma unroll
            for (int jj = 0; jj < 4; jj++) {
                int ch = 8 * (4 * w + jj) + 2 * c;
                g_ps[bid * HDIM + ch]     = make_float2(sL[jj], qL[jj]);
                g_ps[bid * HDIM + ch + 1] = make_float2(sH[jj], qH[jj]);
            }
        }
    } else if (bid < SGRID + 32) {
        // ---------------- X = nW2 @ Wv : 8 rows per block ------------------
        int r = (bid - SGRID) * 8 + w;
        for (int i = l; i < HDIM; i += 32) rows[w][i] = __ldg(nW2 + r * HDIM + i);
        __syncwarp();
        float acc[8] = {0.f, 0.f, 0.f, 0.f, 0.f, 0.f, 0.f, 0.f};
#pragma unroll 4
        for (int k = 0; k < HDIM; k++) {
            float a = rows[w][k];
            const float4* wv = (const float4*)(Wv + k * HDIM);
            float4 v0 = __ldg(wv + l);
            float4 v1 = __ldg(wv + l + 32);
            acc[0] = fmaf(a, v0.x, acc[0]); acc[1] = fmaf(a, v0.y, acc[1]);
            acc[2] = fmaf(a, v0.z, acc[2]); acc[3] = fmaf(a, v0.w, acc[3]);
            acc[4] = fmaf(a, v1.x, acc[4]); acc[5] = fmaf(a, v1.y, acc[5]);
            acc[6] = fmaf(a, v1.z, acc[6]); acc[7] = fmaf(a, v1.w, acc[7]);
        }
        float4* xo = (float4*)(g_X + r * HDIM);
        xo[l]      = make_float4(acc[0], acc[1], acc[2], acc[3]);
        xo[l + 32] = make_float4(acc[4], acc[5], acc[6], acc[7]);
    } else if (bid < SGRID + 64) {
        // ---------------- Y = Wo @ Wp : fold-style, 8 rows per block -------
        const u64* Bv = (const u64*)Wp;
        for (int i = t; i < HDIM * 4; i += 256) Bs[i] = Bv[i];
        __syncthreads();
        int h = (bid - SGRID - 32) * 8 + w;
        const float* Ar = Wo + h * HDIM;
        u64 a0 = 0, a1 = 0, a2 = 0, a3 = 0;
#pragma unroll
        for (int i = 0; i < 8; i++) {
            int k = l + 32 * i;
            float a = __ldg(Ar + k);
            u64 aa = pk(a, a);
            a0 = f2fma(aa, Bs[k * 4 + 0], a0);
            a1 = f2fma(aa, Bs[k * 4 + 1], a1);
            a2 = f2fma(aa, Bs[k * 4 + 2], a2);
            a3 = f2fma(aa, Bs[k * 4 + 3], a3);
        }
        float r[8];
        upk(a0, r[0], r[1]); upk(a1, r[2], r[3]);
        upk(a2, r[4], r[5]); upk(a3, r[6], r[7]);
#pragma unroll
        for (int off = 16; off; off >>= 1)
#pragma unroll
            for (int d = 0; d < 8; d++) r[d] += __shfl_xor_sync(0xffffffffu, r[d], off);
        if (l == 0) {
            float4* o = (float4*)(g_Y + h * 8);
            o[0] = make_float4(r[0], r[1], r[2], r[3]);
            o[1] = make_float4(r[4], r[5], r[6], r[7]);
        }
    } else {
        // ---------------- u = b2 @ Wv : one block, thread per column -------
        float acc = 0.f;
#pragma unroll 8
        for (int k = 0; k < HDIM; k++)
            acc = fmaf(__ldg(b2 + k), __ldg(Wv + k * HDIM + t), acc);
        g_u[t] = acc;
    }
}

// ------------------------- reduce: BN finalize + M/Meff/v row per channel --
__global__ void __launch_bounds__(256) reduce_kernel(const float* __restrict__ gamma,
                                                     const float* __restrict__ beta,
                                                     const float* __restrict__ nf,
                                                     const int* __restrict__ ei0,
                                                     const int* __restrict__ ei1,
                                                     const float* __restrict__ W1,
                                                     const float* __restrict__ b1,
                                                     const float* __restrict__ bv,
                                                     const float* __restrict__ bo,
                                                     const float* __restrict__ Wp,
                                                     int fullE, int E) {
    __shared__ float ss[8], qq[8], Mrow[8];
    __shared__ float sh_scl, sh_shf;
    int h = blockIdx.x, t = threadIdx.x;
    int w = t >> 5, lane = t & 31;

    float2 p0 = g_ps[t * HDIM + h];
    float2 p1 = g_ps[(t + 256) * HDIM + h];
    float s = p0.x + p1.x, q = p0.y + p1.y;
#pragma unroll
    for (int off = 16; off; off >>= 1) {
        s += __shfl_xor_sync(0xffffffffu, s, off);
        q += __shfl_xor_sync(0xffffffffu, q, off);
    }
    if (lane == 0) { ss[w] = s; qq[w] = q; }

    // M[h, d] = X[h,:] @ Y[:, d] : warp d
    {
        float acc = 0.f;
#pragma unroll
        for (int i = 0; i < 8; i++) {
            int k2 = lane + 32 * i;
            acc = fmaf(g_X[h * HDIM + k2], g_Y[k2 * 8 + w], acc);
        }
#pragma unroll
        for (int off = 16; off; off >>= 1) acc += __shfl_xor_sync(0xffffffffu, acc, off);
        if (lane == 0) Mrow[w] = acc;
    }
    __syncthreads();

    if (t == 0) {
        float sv = 0.f, qv = 0.f;
#pragma unroll
        for (int i = 0; i < 8; i++) { sv += ss[i]; qv += qq[i]; }
        for (int e = fullE; e < E; e++) {   // scalar tail (empty when E%16==0)
            int si = __ldg(ei0 + e), ti = __ldg(ei1 + e);
            float z = __ldg(b1 + h);
#pragma unroll
            for (int k = 0; k < 8; k++)
                z = fmaf(0.5f * (__ldg(nf + si * 8 + k) + __ldg(nf + ti * 8 + k)),
                         __ldg(W1 + k * HDIM + h), z);
            float hv = fmaxf(z, 0.f);
            sv += hv; qv = fmaf(hv, hv, qv);
        }
        float invE = 1.0f / (float)E;
        float mu = sv * invE;
        float var = fmaxf(qv * invE - mu * mu, 0.f);
        float scl = gamma[h] * rsqrtf(var + 1e-5f);
        sh_scl = scl;
        sh_shf = beta[h] - mu * scl;
    }
    __syncthreads();

    if (t < 4)
        g_Meff[h * 4 + t] = pk(0.5f * sh_scl * Mrow[2 * t],
                               0.5f * sh_scl * Mrow[2 * t + 1]);
    if (t < DDIM)
        g_v[h * 8 + t] = sh_shf * Mrow[t]
                       + (g_u[h] + __ldg(bv + h)) * g_Y[h * 8 + t]
                       + __ldg(bo + h) * __ldg(Wp + h * 8 + t);
}

// ------------------------- final: c2 = 0.5*(bp + sum_h v[h]) ---------------
__global__ void __launch_bounds__(256) final_kernel(const float* __restrict__ bp) {
    int t = threadIdx.x, w = t >> 5, lane = t & 31;
    if (w < DDIM) {
        float r = 0.f;
#pragma unroll
        for (int i = 0; i < 8; i++) r += g_v[(lane + 32 * i) * 8 + w];
#pragma unroll
        for (int off = 16; off; off >>= 1) r += __shfl_xor_sync(0xffffffffu, r, off);
        if (lane == 0) g_c2[w] = 0.5f * (__ldg(bp + w) + r);
    }
}

// ------------------------- pass B: main (byte-identical R8/R4) -------------
__global__ void __launch_bounds__(256, 2) main_kernel(const float* __restrict__ edge_attr,
                                                      const float* __restrict__ nf,
                                                      const int* __restrict__ ei0,
                                                      const int* __restrict__ ei1,
                                                      const float* __restrict__ W1,
                                                      const float* __restrict__ b1,
                                                      float* __restrict__ out,
                                                      int E) {
    __shared__ u64 wp[HDIM * 4];
    __shared__ u64 mp[HDIM * 4];
    __shared__ float b1s[HDIM];
    int t = threadIdx.x;
    for (int idx = t; idx < HDIM * 4; idx += 256) {
        int h = idx >> 2, p = idx & 3;
        wp[idx] = pk(0.5f * W1[(2 * p) * HDIM + h], 0.5f * W1[(2 * p + 1) * HDIM + h]);
        mp[idx] = g_Meff[idx];
    }
    b1s[t] = b1[t];
    __syncthreads();

    int base = (blockIdx.x * 256 + t) * 4;
    if (base >= E) return;

    int ee[4];
#pragma unroll
    for (int i = 0; i < 4; i++) ee[i] = min(base + i, E - 1);

    const float4* nfp = (const float4*)nf;
    u64 n[4][4];
#pragma unroll
    for (int i = 0; i < 4; i++) {
        int s = __ldg(ei0 + ee[i]), g = __ldg(ei1 + ee[i]);
        float4 a0 = __ldg(nfp + 2 * s), a1 = __ldg(nfp + 2 * s + 1);
        float4 c0 = __ldg(nfp + 2 * g), c1 = __ldg(nfp + 2 * g + 1);
        n[i][0] = pk(a0.x + c0.x, a0.y + c0.y);
        n[i][1] = pk(a0.z + c0.z, a0.w + c0.w);
        n[i][2] = pk(a1.x + c1.x, a1.y + c1.y);
        n[i][3] = pk(a1.z + c1.z, a1.w + c1.w);
    }

    u64 acc[4][4];
#pragma unroll
    for (int i = 0; i < 4; i++)
#pragma unroll
        for (int p = 0; p < 4; p++) acc[i][p] = 0;

#pragma unroll 2
    for (int h = 0; h < HDIM; h++) {
        u64 w0 = wp[h * 4 + 0], w1 = wp[h * 4 + 1], w2 = wp[h * 4 + 2], w3 = wp[h * 4 + 3];
        u64 m0 = mp[h * 4 + 0], m1 = mp[h * 4 + 1], m2 = mp[h * 4 + 2], m3 = mp[h * 4 + 3];
        float bb = b1s[h];
#pragma unroll
        for (int i = 0; i < 4; i++) {
            u64 s_ = f2mul(n[i][0], w0);
            s_ = f2fma(n[i][1], w1, s_);
            s_ = f2fma(n[i][2], w2, s_);
            s_ = f2fma(n[i][3], w3, s_);
            float lo, hi; upk(s_, lo, hi);
            float h1 = fmaxf(lo + hi + bb, 0.f);
            u64 hh = pk(h1, h1);
            acc[i][0] = f2fma(hh, m0, acc[i][0]);
            acc[i][1] = f2fma(hh, m1, acc[i][1]);
            acc[i][2] = f2fma(hh, m2, acc[i][2]);
            acc[i][3] = f2fma(hh, m3, acc[i][3]);
        }
    }

    float cz[8];
#pragma unroll
    for (int d = 0; d < 8; d++) cz[d] = g_c2[d];

    const float4* eap = (const float4*)edge_attr;
    float4* outp = (float4*)out;
#pragma unroll
    for (int i = 0; i < 4; i++) {
        int e = base + i;
        if (e >= E) break;
        float4 e0 = __ldg(eap + e * 2), e1 = __ldg(eap + e * 2 + 1);
        float x0, x1, x2, x3, x4, x5, x6, x7;
        upk(acc[i][0], x0, x1); upk(acc[i][1], x2, x3);
        upk(acc[i][2], x4, x5); upk(acc[i][3], x6, x7);
        float4 o0, o1;
        o0.x = e0.x + x0 + cz[0]; o0.y = e0.y + x1 + cz[1];
        o0.z = e0.z + x2 + cz[2]; o0.w = e0.w + x3 + cz[3];
        o1.x = e1.x + x4 + cz[4]; o1.y = e1.y + x5 + cz[5];
        o1.z = e1.z + x6 + cz[6]; o1.w = e1.w + x7 + cz[7];
        outp[e * 2] = o0; outp[e * 2 + 1] = o1;
    }
}

// ------------------------- launch ------------------------------------------
extern "C" void kernel_launch(void* const* d_in, const int* in_sizes, int n_in,
                              void* d_out, int out_size) {
    const float* edge_attr = (const float*)d_in[0];
    const float* nf        = (const float*)d_in[1];
    const int*   ei        = (const int*)  d_in[2];
    // d_in[3..8] = edge encoder params: dead code in the reference, unused.
    const float* nW1   = (const float*)d_in[9];
    const float* nb1   = (const float*)d_in[10];
    const float* ngam  = (const float*)d_in[11];
    const float* nbet  = (const float*)d_in[12];
    const float* nW2   = (const float*)d_in[13];
    const float* nb2   = (const float*)d_in[14];
    const float* Wv    = (const float*)d_in[15];
    const float* bv    = (const float*)d_in[16];
    const float* Wo    = (const float*)d_in[17];
    const float* bo    = (const float*)d_in[18];
    const float* Wp    = (const float*)d_in[19];
    const float* bp    = (const float*)d_in[20];
    (void)n_in; (void)out_size;

    int E = in_sizes[0] / DDIM;
    const int* ei0 = ei;
    const int* ei1 = ei + E;
    float* out = (float*)d_out;
    int fullE = (E / 16) * 16;

    // stats + X + Y + u in one launch (X/Y/u blocks ride the tail wave)
    mega_kernel<<<SGRID + 65, 256>>>(nf, ei0, ei1, nW1, nb1,
                                     Wo, Wv, nW2, Wp, nb2, fullE);

    // per-channel: BN finalize + M row + Meff pack + c2 contribution
    reduce_kernel<<<HDIM, 256>>>(ngam, nbet, nf, ei0, ei1, nW1, nb1,
                                 bv, bo, Wp, fullE, E);

    // c2 gather (tiny)
    final_kernel<<<1, 256>>>(bp);

    // main fused pass, 4 edges / thread (byte-identical R8)
    int gridB = (E + 1023) / 1024;
    main_kernel<<<gridB, 256>>>(edge_attr, nf, ei0, ei1, nW1, nb1, out, E);
}

// round 14
// speedup vs baseline: 1.7699x; 1.0407x over previous
#include <cuda_runtime.h>
#include <math.h>

// ---------------------------------------------------------------------------
// CausalEdgeAttention — algebraically reduced:
//   out = edge_attr + relu(nc@W1eff + b1) @ Meff + c2
//   M = nW2@Wv@Wo@Wp  reassociated as  M = X@Y,  X = nW2@Wv,  Y = Wo@Wp
//   u = b2@Wv  (so b2@R2 == u@Y);  c2 = 0.5*(bp + Σ_h v[h]),
//   v[h,:] = shift[h]*M[h,:] + (u[h]+bv[h])*Y[h,:] + bo[h]*Wp[h,:]
// Edge encoder in the reference is dead code -> skipped.
// mega: stats (tf32 MMA) + X/Y/u tail-wave blocks (R13 proven).
// reduce/final: R13 proven.
// main: 2 edges/thread, __launch_bounds__(256,4) -> 32 warps/SM (R13 ncu
//       showed occ=21.5%, issue=50.7% at 4 edges/104 regs: occupancy-bound).
// ---------------------------------------------------------------------------

#define HDIM 256
#define DDIM 8
#define SGRID 512

typedef unsigned long long u64;
typedef unsigned int u32;

__device__ __forceinline__ u64 pk(float lo, float hi) {
    u64 r; asm("mov.b64 %0,{%1,%2};" : "=l"(r) : "f"(lo), "f"(hi)); return r;
}
__device__ __forceinline__ void upk(u64 v, float& lo, float& hi) {
    asm("mov.b64 {%0,%1},%2;" : "=f"(lo), "=f"(hi) : "l"(v));
}
__device__ __forceinline__ u64 f2mul(u64 a, u64 b) {
    u64 d; asm("mul.rn.f32x2 %0,%1,%2;" : "=l"(d) : "l"(a), "l"(b)); return d;
}
__device__ __forceinline__ u64 f2fma(u64 a, u64 b, u64 c) {
    u64 d; asm("fma.rn.f32x2 %0,%1,%2,%3;" : "=l"(d) : "l"(a), "l"(b), "l"(c)); return d;
}
__device__ __forceinline__ u32 cvt_tf32(float f) {
    u32 r; asm("cvt.rna.tf32.f32 %0, %1;" : "=r"(r) : "f"(f)); return r;
}

// ------------------------- scratch (device globals; no allocs) -------------
__device__ float  g_X[HDIM * HDIM];    // nW2 @ Wv
__device__ float  g_Y[HDIM * DDIM];    // Wo @ Wp
__device__ float  g_u[HDIM];           // b2 @ Wv
__device__ float  g_v[HDIM * DDIM];    // per-h c2 contributions
__device__ float2 g_ps[SGRID * HDIM];  // BN partials (sum, sumsq)
__device__ u64    g_Meff[HDIM * 4];    // packed d-pairs: 0.5*scale[h]*M[h][:]
__device__ float  g_c2[DDIM];

// ------------------------- mega: stats (tf32 MMA) + X + Y + u --------------
__global__ void __launch_bounds__(256) mega_kernel(const float* __restrict__ nf,
                                                   const int* __restrict__ ei0,
                                                   const int* __restrict__ ei1,
                                                   const float* __restrict__ W1,
                                                   const float* __restrict__ b1,
                                                   const float* __restrict__ Wo,
                                                   const float* __restrict__ Wv,
                                                   const float* __restrict__ nW2,
                                                   const float* __restrict__ Wp,
                                                   const float* __restrict__ b2,
                                                   int fullE) {
    __shared__ float aS[4][8][32];     // stats A-frags (4KB)
    __shared__ float rows[8][256];     // X: staged nW2 rows (8KB)
    __shared__ u64   Bs[HDIM * 4];     // Y: staged Wp pairs (8KB)
    int bid = blockIdx.x;
    int t = threadIdx.x, w = t >> 5, l = t & 31;

    if (bid < SGRID) {
        // ---------------- BN statistics via tf32 MMA (R8 proven) ----------
        int g = l >> 2, c = l & 3;
        u32 Bf0[4], Bf1[4];
        float cbl[4], cbh[4];
#pragma unroll
        for (int jj = 0; jj < 4; jj++) {
            int j = 4 * w + jj, n = 8 * j + g;
            Bf0[jj] = cvt_tf32(0.5f * __ldg(W1 + c * HDIM + n));
            Bf1[jj] = cvt_tf32(0.5f * __ldg(W1 + (c + 4) * HDIM + n));
            cbl[jj] = __ldg(b1 + 8 * j + 2 * c);
            cbh[jj] = __ldg(b1 + 8 * j + 2 * c + 1);
        }
        float sL[4] = {0.f, 0.f, 0.f, 0.f}, sH[4] = {0.f, 0.f, 0.f, 0.f};
        float qL[4] = {0.f, 0.f, 0.f, 0.f}, qH[4] = {0.f, 0.f, 0.f, 0.f};
        const float4* nfp = (const float4*)nf;

        for (int base = bid * 128; base < fullE; base += SGRID * 128) {
            __syncthreads();
            if (t < 128) {
                int e = base + t;
                if (e < fullE) {
                    int r = t & 15, tt = t >> 4;
                    int si = __ldg(ei0 + e), ti = __ldg(ei1 + e);
                    float4 s0 = __ldg(nfp + 2 * si), s1 = __ldg(nfp + 2 * si + 1);
                    float4 u0 = __ldg(nfp + 2 * ti), u1 = __ldg(nfp + 2 * ti + 1);
                    float v[8];
                    v[0] = s0.x + u0.x; v[1] = s0.y + u0.y;
                    v[2] = s0.z + u0.z; v[3] = s0.w + u0.w;
                    v[4] = s1.x + u1.x; v[5] = s1.y + u1.y;
                    v[6] = s1.z + u1.z; v[7] = s1.w + u1.w;
                    int rr = r & 7, hi = r >> 3;
#pragma unroll
                    for (int cc = 0; cc < 4; cc++) {
                        aS[hi][tt][rr * 4 + cc]     = __uint_as_float(cvt_tf32(v[cc]));
                        aS[2 + hi][tt][rr * 4 + cc] = __uint_as_float(cvt_tf32(v[cc + 4]));
                    }
                }
            }
            __syncthreads();
#pragma unroll
            for (int tt = 0; tt < 8; tt++) {
                if (base + 16 * tt >= fullE) break;
                u32 A0 = __float_as_uint(aS[0][tt][l]);
                u32 A1 = __float_as_uint(aS[1][tt][l]);
                u32 A2 = __float_as_uint(aS[2][tt][l]);
                u32 A3 = __float_as_uint(aS[3][tt][l]);
#pragma unroll
                for (int jj = 0; jj < 4; jj++) {
                    float d0, d1, d2, d3;
                    asm volatile(
                        "mma.sync.aligned.m16n8k8.row.col.f32.tf32.tf32.f32 "
                        "{%0,%1,%2,%3}, {%4,%5,%6,%7}, {%8,%9}, {%10,%11,%12,%13};\n"
                        : "=f"(d0), "=f"(d1), "=f"(d2), "=f"(d3)
                        : "r"(A0), "r"(A1), "r"(A2), "r"(A3),
                          "r"(Bf0[jj]), "r"(Bf1[jj]),
                          "f"(cbl[jj]), "f"(cbh[jj]), "f"(cbl[jj]), "f"(cbh[jj]));
                    float r0 = fmaxf(d0, 0.f), r1 = fmaxf(d1, 0.f);
                    float r2 = fmaxf(d2, 0.f), r3 = fmaxf(d3, 0.f);
                    sL[jj] += r0 + r2;
                    sH[jj] += r1 + r3;
                    qL[jj] = fmaf(r0, r0, qL[jj]); qL[jj] = fmaf(r2, r2, qL[jj]);
                    qH[jj] = fmaf(r1, r1, qH[jj]); qH[jj] = fmaf(r3, r3, qH[jj]);
                }
            }
        }
#pragma unroll
        for (int jj = 0; jj < 4; jj++)
#pragma unroll
            for (int off = 4; off <= 16; off <<= 1) {
                sL[jj] += __shfl_xor_sync(0xffffffffu, sL[jj], off);
                sH[jj] += __shfl_xor_sync(0xffffffffu, sH[jj], off);
                qL[jj] += __shfl_xor_sync(0xffffffffu, qL[jj], off);
                qH[jj] += __shfl_xor_sync(0xffffffffu, qH[jj], off);
            }
        if (g == 0) {
#pragma unroll
            for (int jj = 0; jj < 4; jj++) {
                int ch = 8 * (4 * w + jj) + 2 * c;
                g_ps[bid * HDIM + ch]     = make_float2(sL[jj], qL[jj]);
                g_ps[bid * HDIM + ch + 1] = make_float2(sH[jj], qH[jj]);
            }
        }
    } else if (bid < SGRID + 32) {
        // ---------------- X = nW2 @ Wv : 8 rows per block ------------------
        int r = (bid - SGRID) * 8 + w;
        for (int i = l; i < HDIM; i += 32) rows[w][i] = __ldg(nW2 + r * HDIM + i);
        __syncwarp();
        float acc[8] = {0.f, 0.f, 0.f, 0.f, 0.f, 0.f, 0.f, 0.f};
#pragma unroll 4
        for (int k = 0; k < HDIM; k++) {
            float a = rows[w][k];
            const float4* wv = (const float4*)(Wv + k * HDIM);
            float4 v0 = __ldg(wv + l);
            float4 v1 = __ldg(wv + l + 32);
            acc[0] = fmaf(a, v0.x, acc[0]); acc[1] = fmaf(a, v0.y, acc[1]);
            acc[2] = fmaf(a, v0.z, acc[2]); acc[3] = fmaf(a, v0.w, acc[3]);
            acc[4] = fmaf(a, v1.x, acc[4]); acc[5] = fmaf(a, v1.y, acc[5]);
            acc[6] = fmaf(a, v1.z, acc[6]); acc[7] = fmaf(a, v1.w, acc[7]);
        }
        float4* xo = (float4*)(g_X + r * HDIM);
        xo[l]      = make_float4(acc[0], acc[1], acc[2], acc[3]);
        xo[l + 32] = make_float4(acc[4], acc[5], acc[6], acc[7]);
    } else if (bid < SGRID + 64) {
        // ---------------- Y = Wo @ Wp : fold-style, 8 rows per block -------
        const u64* Bv = (const u64*)Wp;
        for (int i = t; i < HDIM * 4; i += 256) Bs[i] = Bv[i];
        __syncthreads();
        int h = (bid - SGRID - 32) * 8 + w;
        const float* Ar = Wo + h * HDIM;
        u64 a0 = 0, a1 = 0, a2 = 0, a3 = 0;
#pragma unroll
        for (int i = 0; i < 8; i++) {
            int k = l + 32 * i;
            float a = __ldg(Ar + k);
            u64 aa = pk(a, a);
            a0 = f2fma(aa, Bs[k * 4 + 0], a0);
            a1 = f2fma(aa, Bs[k * 4 + 1], a1);
            a2 = f2fma(aa, Bs[k * 4 + 2], a2);
            a3 = f2fma(aa, Bs[k * 4 + 3], a3);
        }
        float r[8];
        upk(a0, r[0], r[1]); upk(a1, r[2], r[3]);
        upk(a2, r[4], r[5]); upk(a3, r[6], r[7]);
#pragma unroll
        for (int off = 16; off; off >>= 1)
#pragma unroll
            for (int d = 0; d < 8; d++) r[d] += __shfl_xor_sync(0xffffffffu, r[d], off);
        if (l == 0) {
            float4* o = (float4*)(g_Y + h * 8);
            o[0] = make_float4(r[0], r[1], r[2], r[3]);
            o[1] = make_float4(r[4], r[5], r[6], r[7]);
        }
    } else {
        // ---------------- u = b2 @ Wv : one block, thread per column -------
        float acc = 0.f;
#pragma unroll 8
        for (int k = 0; k < HDIM; k++)
            acc = fmaf(__ldg(b2 + k), __ldg(Wv + k * HDIM + t), acc);
        g_u[t] = acc;
    }
}

// ------------------------- reduce: BN finalize + M/Meff/v row per channel --
__global__ void __launch_bounds__(256) reduce_kernel(const float* __restrict__ gamma,
                                                     const float* __restrict__ beta,
                                                     const float* __restrict__ nf,
                                                     const int* __restrict__ ei0,
                                                     const int* __restrict__ ei1,
                                                     const float* __restrict__ W1,
                                                     const float* __restrict__ b1,
                                                     const float* __restrict__ bv,
                                                     const float* __restrict__ bo,
                                                     const float* __restrict__ Wp,
                                                     int fullE, int E) {
    __shared__ float ss[8], qq[8], Mrow[8];
    __shared__ float sh_scl, sh_shf;
    int h = blockIdx.x, t = threadIdx.x;
    int w = t >> 5, lane = t & 31;

    float2 p0 = g_ps[t * HDIM + h];
    float2 p1 = g_ps[(t + 256) * HDIM + h];
    float s = p0.x + p1.x, q = p0.y + p1.y;
#pragma unroll
    for (int off = 16; off; off >>= 1) {
        s += __shfl_xor_sync(0xffffffffu, s, off);
        q += __shfl_xor_sync(0xffffffffu, q, off);
    }
    if (lane == 0) { ss[w] = s; qq[w] = q; }

    // M[h, d] = X[h,:] @ Y[:, d] : warp d
    {
        float acc = 0.f;
#pragma unroll
        for (int i = 0; i < 8; i++) {
            int k2 = lane + 32 * i;
            acc = fmaf(g_X[h * HDIM + k2], g_Y[k2 * 8 + w], acc);
        }
#pragma unroll
        for (int off = 16; off; off >>= 1) acc += __shfl_xor_sync(0xffffffffu, acc, off);
        if (lane == 0) Mrow[w] = acc;
    }
    __syncthreads();

    if (t == 0) {
        float sv = 0.f, qv = 0.f;
#pragma unroll
        for (int i = 0; i < 8; i++) { sv += ss[i]; qv += qq[i]; }
        for (int e = fullE; e < E; e++) {   // scalar tail (empty when E%16==0)
            int si = __ldg(ei0 + e), ti = __ldg(ei1 + e);
            float z = __ldg(b1 + h);
#pragma unroll
            for (int k = 0; k < 8; k++)
                z = fmaf(0.5f * (__ldg(nf + si * 8 + k) + __ldg(nf + ti * 8 + k)),
                         __ldg(W1 + k * HDIM + h), z);
            float hv = fmaxf(z, 0.f);
            sv += hv; qv = fmaf(hv, hv, qv);
        }
        float invE = 1.0f / (float)E;
        float mu = sv * invE;
        float var = fmaxf(qv * invE - mu * mu, 0.f);
        float scl = gamma[h] * rsqrtf(var + 1e-5f);
        sh_scl = scl;
        sh_shf = beta[h] - mu * scl;
    }
    __syncthreads();

    if (t < 4)
        g_Meff[h * 4 + t] = pk(0.5f * sh_scl * Mrow[2 * t],
                               0.5f * sh_scl * Mrow[2 * t + 1]);
    if (t < DDIM)
        g_v[h * 8 + t] = sh_shf * Mrow[t]
                       + (g_u[h] + __ldg(bv + h)) * g_Y[h * 8 + t]
                       + __ldg(bo + h) * __ldg(Wp + h * 8 + t);
}

// ------------------------- final: c2 = 0.5*(bp + sum_h v[h]) ---------------
__global__ void __launch_bounds__(256) final_kernel(const float* __restrict__ bp) {
    int t = threadIdx.x, w = t >> 5, lane = t & 31;
    if (w < DDIM) {
        float r = 0.f;
#pragma unroll
        for (int i = 0; i < 8; i++) r += g_v[(lane + 32 * i) * 8 + w];
#pragma unroll
        for (int off = 16; off; off >>= 1) r += __shfl_xor_sync(0xffffffffu, r, off);
        if (lane == 0) g_c2[w] = 0.5f * (__ldg(bp + w) + r);
    }
}

// ------------------------- pass B: main (2 edges/thread, high occupancy) ---
__global__ void __launch_bounds__(256, 4) main_kernel(const float* __restrict__ edge_attr,
                                                      const float* __restrict__ nf,
                                                      const int* __restrict__ ei0,
                                                      const int* __restrict__ ei1,
                                                      const float* __restrict__ W1,
                                                      const float* __restrict__ b1,
                                                      float* __restrict__ out,
                                                      int E) {
    __shared__ u64 wp[HDIM * 4];
    __shared__ u64 mp[HDIM * 4];
    __shared__ float b1s[HDIM];
    int t = threadIdx.x;
    for (int idx = t; idx < HDIM * 4; idx += 256) {
        int h = idx >> 2, p = idx & 3;
        wp[idx] = pk(0.5f * W1[(2 * p) * HDIM + h], 0.5f * W1[(2 * p + 1) * HDIM + h]);
        mp[idx] = g_Meff[idx];
    }
    b1s[t] = b1[t];
    __syncthreads();

    int base = (blockIdx.x * 256 + t) * 2;
    if (base >= E) return;

    int e0 = base;
    int e1 = min(base + 1, E - 1);

    const float4* nfp = (const float4*)nf;
    u64 nA[4], nB[4];
    {
        int s = __ldg(ei0 + e0), g = __ldg(ei1 + e0);
        float4 a0 = __ldg(nfp + 2 * s), a1 = __ldg(nfp + 2 * s + 1);
        float4 c0 = __ldg(nfp + 2 * g), c1 = __ldg(nfp + 2 * g + 1);
        nA[0] = pk(a0.x + c0.x, a0.y + c0.y);
        nA[1] = pk(a0.z + c0.z, a0.w + c0.w);
        nA[2] = pk(a1.x + c1.x, a1.y + c1.y);
        nA[3] = pk(a1.z + c1.z, a1.w + c1.w);
    }
    {
        int s = __ldg(ei0 + e1), g = __ldg(ei1 + e1);
        float4 a0 = __ldg(nfp + 2 * s), a1 = __ldg(nfp + 2 * s + 1);
        float4 c0 = __ldg(nfp + 2 * g), c1 = __ldg(nfp + 2 * g + 1);
        nB[0] = pk(a0.x + c0.x, a0.y + c0.y);
        nB[1] = pk(a0.z + c0.z, a0.w + c0.w);
        nB[2] = pk(a1.x + c1.x, a1.y + c1.y);
        nB[3] = pk(a1.z + c1.z, a1.w + c1.w);
    }

    u64 aA0 = 0, aA1 = 0, aA2 = 0, aA3 = 0;
    u64 aB0 = 0, aB1 = 0, aB2 = 0, aB3 = 0;

#pragma unroll 2
    for (int h = 0; h < HDIM; h++) {
        u64 w0 = wp[h * 4 + 0], w1 = wp[h * 4 + 1], w2 = wp[h * 4 + 2], w3 = wp[h * 4 + 3];
        u64 m0 = mp[h * 4 + 0], m1 = mp[h * 4 + 1], m2 = mp[h * 4 + 2], m3 = mp[h * 4 + 3];
        float bb = b1s[h];

        u64 sA = f2mul(nA[0], w0);
        sA = f2fma(nA[1], w1, sA);
        sA = f2fma(nA[2], w2, sA);
        sA = f2fma(nA[3], w3, sA);
        float loA, hiA; upk(sA, loA, hiA);
        float h1A = fmaxf(loA + hiA + bb, 0.f);
        u64 hA = pk(h1A, h1A);
        aA0 = f2fma(hA, m0, aA0);
        aA1 = f2fma(hA, m1, aA1);
        aA2 = f2fma(hA, m2, aA2);
        aA3 = f2fma(hA, m3, aA3);

        u64 sB = f2mul(nB[0], w0);
        sB = f2fma(nB[1], w1, sB);
        sB = f2fma(nB[2], w2, sB);
        sB = f2fma(nB[3], w3, sB);
        float loB, hiB; upk(sB, loB, hiB);
        float h1B = fmaxf(loB + hiB + bb, 0.f);
        u64 hB = pk(h1B, h1B);
        aB0 = f2fma(hB, m0, aB0);
        aB1 = f2fma(hB, m1, aB1);
        aB2 = f2fma(hB, m2, aB2);
        aB3 = f2fma(hB, m3, aB3);
    }

    float cz[8];
#pragma unroll
    for (int d = 0; d < 8; d++) cz[d] = g_c2[d];

    const float4* eap = (const float4*)edge_attr;
    float4* outp = (float4*)out;
    {
        float4 ea0 = __ldg(eap + e0 * 2), ea1 = __ldg(eap + e0 * 2 + 1);
        float x0, x1, x2, x3, x4, x5, x6, x7;
        upk(aA0, x0, x1); upk(aA1, x2, x3);
        upk(aA2, x4, x5); upk(aA3, x6, x7);
        float4 o0, o1;
        o0.x = ea0.x + x0 + cz[0]; o0.y = ea0.y + x1 + cz[1];
        o0.z = ea0.z + x2 + cz[2]; o0.w = ea0.w + x3 + cz[3];
        o1.x = ea1.x + x4 + cz[4]; o1.y = ea1.y + x5 + cz[5];
        o1.z = ea1.z + x6 + cz[6]; o1.w = ea1.w + x7 + cz[7];
        outp[e0 * 2] = o0; outp[e0 * 2 + 1] = o1;
    }
    if (base + 1 < E) {
        float4 ea0 = __ldg(eap + e1 * 2), ea1 = __ldg(eap + e1 * 2 + 1);
        float x0, x1, x2, x3, x4, x5, x6, x7;
        upk(aB0, x0, x1); upk(aB1, x2, x3);
        upk(aB2, x4, x5); upk(aB3, x6, x7);
        float4 o0, o1;
        o0.x = ea0.x + x0 + cz[0]; o0.y = ea0.y + x1 + cz[1];
        o0.z = ea0.z + x2 + cz[2]; o0.w = ea0.w + x3 + cz[3];
        o1.x = ea1.x + x4 + cz[4]; o1.y = ea1.y + x5 + cz[5];
        o1.z = ea1.z + x6 + cz[6]; o1.w = ea1.w + x7 + cz[7];
        outp[e1 * 2] = o0; outp[e1 * 2 + 1] = o1;
    }
}

// ------------------------- launch ------------------------------------------
extern "C" void kernel_launch(void* const* d_in, const int* in_sizes, int n_in,
                              void* d_out, int out_size) {
    const float* edge_attr = (const float*)d_in[0];
    const float* nf        = (const float*)d_in[1];
    const int*   ei        = (const int*)  d_in[2];
    // d_in[3..8] = edge encoder params: dead code in the reference, unused.
    const float* nW1   = (const float*)d_in[9];
    const float* nb1   = (const float*)d_in[10];
    const float* ngam  = (const float*)d_in[11];
    const float* nbet  = (const float*)d_in[12];
    const float* nW2   = (const float*)d_in[13];
    const float* nb2   = (const float*)d_in[14];
    const float* Wv    = (const float*)d_in[15];
    const float* bv    = (const float*)d_in[16];
    const float* Wo    = (const float*)d_in[17];
    const float* bo    = (const float*)d_in[18];
    const float* Wp    = (const float*)d_in[19];
    const float* bp    = (const float*)d_in[20];
    (void)n_in; (void)out_size;

    int E = in_sizes[0] / DDIM;
    const int* ei0 = ei;
    const int* ei1 = ei + E;
    float* out = (float*)d_out;
    int fullE = (E / 16) * 16;

    // stats + X + Y + u in one launch (X/Y/u blocks ride the tail wave)
    mega_kernel<<<SGRID + 65, 256>>>(nf, ei0, ei1, nW1, nb1,
                                     Wo, Wv, nW2, Wp, nb2, fullE);

    // per-channel: BN finalize + M row + Meff pack + c2 contribution
    reduce_kernel<<<HDIM, 256>>>(ngam, nbet, nf, ei0, ei1, nW1, nb1,
                                 bv, bo, Wp, fullE, E);

    // c2 gather (tiny)
    final_kernel<<<1, 256>>>(bp);

    // main fused pass, 2 edges / thread, 4 blocks/SM
    int gridB = (E + 511) / 512;
    main_kernel<<<gridB, 256>>>(edge_attr, nf, ei0, ei1, nW1, nb1, out, E);
}

// round 16
// speedup vs baseline: 1.7792x; 1.0053x over previous
#include <cuda_runtime.h>
#include <math.h>

// ---------------------------------------------------------------------------
// CausalEdgeAttention — algebraically reduced:
//   out = edge_attr + relu(nc@W1eff + b1) @ Meff + c2
//   M = nW2@Wv@Wo@Wp  reassociated as  M = X@Y,  X = nW2@Wv,  Y = Wo@Wp
//   u = b2@Wv  (so b2@R2 == u@Y);  c2 = 0.5*(bp + Σ_h v[h]),
//   v[h,:] = shift[h]*M[h,:] + (u[h]+bv[h])*Y[h,:] + bo[h]*Wp[h,:]
// Edge encoder in the reference is dead code -> skipped.
// mega: stats (tf32 MMA) + X/Y/u tail-wave blocks (R13 proven).
// reduce/final: R13 proven.
// main: 2 edges/thread, LDS.128 weight staging (5 LDS/h vs 9), bias as
//       f2fma chain seed, __launch_bounds__(256,3) to guarantee no spill.
//       (R14 ncu: occ 40%, L1 65% -> smem-port bound; this halves LDS.)
// ---------------------------------------------------------------------------

#define HDIM 256
#define DDIM 8
#define SGRID 512

typedef unsigned long long u64;
typedef unsigned int u32;

__device__ __forceinline__ u64 pk(float lo, float hi) {
    u64 r; asm("mov.b64 %0,{%1,%2};" : "=l"(r) : "f"(lo), "f"(hi)); return r;
}
__device__ __forceinline__ void upk(u64 v, float& lo, float& hi) {
    asm("mov.b64 {%0,%1},%2;" : "=f"(lo), "=f"(hi) : "l"(v));
}
__device__ __forceinline__ u64 f2mul(u64 a, u64 b) {
    u64 d; asm("mul.rn.f32x2 %0,%1,%2;" : "=l"(d) : "l"(a), "l"(b)); return d;
}
__device__ __forceinline__ u64 f2fma(u64 a, u64 b, u64 c) {
    u64 d; asm("fma.rn.f32x2 %0,%1,%2,%3;" : "=l"(d) : "l"(a), "l"(b), "l"(c)); return d;
}
__device__ __forceinline__ u32 cvt_tf32(float f) {
    u32 r; asm("cvt.rna.tf32.f32 %0, %1;" : "=r"(r) : "f"(f)); return r;
}

// ------------------------- scratch (device globals; no allocs) -------------
__device__ float  g_X[HDIM * HDIM];    // nW2 @ Wv
__device__ float  g_Y[HDIM * DDIM];    // Wo @ Wp
__device__ float  g_u[HDIM];           // b2 @ Wv
__device__ float  g_v[HDIM * DDIM];    // per-h c2 contributions
__device__ float2 g_ps[SGRID * HDIM];  // BN partials (sum, sumsq)
__device__ u64    g_Meff[HDIM * 4];    // packed d-pairs: 0.5*scale[h]*M[h][:]
__device__ float  g_c2[DDIM];

// ------------------------- mega: stats (tf32 MMA) + X + Y + u --------------
__global__ void __launch_bounds__(256) mega_kernel(const float* __restrict__ nf,
                                                   const int* __restrict__ ei0,
                                                   const int* __restrict__ ei1,
                                                   const float* __restrict__ W1,
                                                   const float* __restrict__ b1,
                                                   const float* __restrict__ Wo,
                                                   const float* __restrict__ Wv,
                                                   const float* __restrict__ nW2,
                                                   const float* __restrict__ Wp,
                                                   const float* __restrict__ b2,
                                                   int fullE) {
    __shared__ float aS[4][8][32];     // stats A-frags (4KB)
    __shared__ float rows[8][256];     // X: staged nW2 rows (8KB)
    __shared__ u64   Bs[HDIM * 4];     // Y: staged Wp pairs (8KB)
    int bid = blockIdx.x;
    int t = threadIdx.x, w = t >> 5, l = t & 31;

    if (bid < SGRID) {
        // ---------------- BN statistics via tf32 MMA (R8 proven) ----------
        int g = l >> 2, c = l & 3;
        u32 Bf0[4], Bf1[4];
        float cbl[4], cbh[4];
#pragma unroll
        for (int jj = 0; jj < 4; jj++) {
            int j = 4 * w + jj, n = 8 * j + g;
            Bf0[jj] = cvt_tf32(0.5f * __ldg(W1 + c * HDIM + n));
            Bf1[jj] = cvt_tf32(0.5f * __ldg(W1 + (c + 4) * HDIM + n));
            cbl[jj] = __ldg(b1 + 8 * j + 2 * c);
            cbh[jj] = __ldg(b1 + 8 * j + 2 * c + 1);
        }
        float sL[4] = {0.f, 0.f, 0.f, 0.f}, sH[4] = {0.f, 0.f, 0.f, 0.f};
        float qL[4] = {0.f, 0.f, 0.f, 0.f}, qH[4] = {0.f, 0.f, 0.f, 0.f};
        const float4* nfp = (const float4*)nf;

        for (int base = bid * 128; base < fullE; base += SGRID * 128) {
            __syncthreads();
            if (t < 128) {
                int e = base + t;
                if (e < fullE) {
                    int r = t & 15, tt = t >> 4;
                    int si = __ldg(ei0 + e), ti = __ldg(ei1 + e);
                    float4 s0 = __ldg(nfp + 2 * si), s1 = __ldg(nfp + 2 * si + 1);
                    float4 u0 = __ldg(nfp + 2 * ti), u1 = __ldg(nfp + 2 * ti + 1);
                    float v[8];
                    v[0] = s0.x + u0.x; v[1] = s0.y + u0.y;
                    v[2] = s0.z + u0.z; v[3] = s0.w + u0.w;
                    v[4] = s1.x + u1.x; v[5] = s1.y + u1.y;
                    v[6] = s1.z + u1.z; v[7] = s1.w + u1.w;
                    int rr = r & 7, hi = r >> 3;
#pragma unroll
                    for (int cc = 0; cc < 4; cc++) {
                        aS[hi][tt][rr * 4 + cc]     = __uint_as_float(cvt_tf32(v[cc]));
                        aS[2 + hi][tt][rr * 4 + cc] = __uint_as_float(cvt_tf32(v[cc + 4]));
                    }
                }
            }
            __syncthreads();
#pragma unroll
            for (int tt = 0; tt < 8; tt++) {
                if (base + 16 * tt >= fullE) break;
                u32 A0 = __float_as_uint(aS[0][tt][l]);
                u32 A1 = __float_as_uint(aS[1][tt][l]);
                u32 A2 = __float_as_uint(aS[2][tt][l]);
                u32 A3 = __float_as_uint(aS[3][tt][l]);
#pragma unroll
                for (int jj = 0; jj < 4; jj++) {
                    float d0, d1, d2, d3;
                    asm volatile(
                        "mma.sync.aligned.m16n8k8.row.col.f32.tf32.tf32.f32 "
                        "{%0,%1,%2,%3}, {%4,%5,%6,%7}, {%8,%9}, {%10,%11,%12,%13};\n"
                        : "=f"(d0), "=f"(d1), "=f"(d2), "=f"(d3)
                        : "r"(A0), "r"(A1), "r"(A2), "r"(A3),
                          "r"(Bf0[jj]), "r"(Bf1[jj]),
                          "f"(cbl[jj]), "f"(cbh[jj]), "f"(cbl[jj]), "f"(cbh[jj]));
                    float r0 = fmaxf(d0, 0.f), r1 = fmaxf(d1, 0.f);
                    float r2 = fmaxf(d2, 0.f), r3 = fmaxf(d3, 0.f);
                    sL[jj] += r0 + r2;
                    sH[jj] += r1 + r3;
                    qL[jj] = fmaf(r0, r0, qL[jj]); qL[jj] = fmaf(r2, r2, qL[jj]);
                    qH[jj] = fmaf(r1, r1, qH[jj]); qH[jj] = fmaf(r3, r3, qH[jj]);
                }
            }
        }
#pragma unroll
        for (int jj = 0; jj < 4; jj++)
#pragma unroll
            for (int off = 4; off <= 16; off <<= 1) {
                sL[jj] += __shfl_xor_sync(0xffffffffu, sL[jj], off);
                sH[jj] += __shfl_xor_sync(0xffffffffu, sH[jj], off);
                qL[jj] += __shfl_xor_sync(0xffffffffu, qL[jj], off);
                qH[jj] += __shfl_xor_sync(0xffffffffu, qH[jj], off);
            }
        if (g == 0) {
#pragma unroll
            for (int jj = 0; jj < 4; jj++) {
                int ch = 8 * (4 * w + jj) + 2 * c;
                g_ps[bid * HDIM + ch]     = make_float2(sL[jj], qL[jj]);
                g_ps[bid * HDIM + ch + 1] = make_float2(sH[jj], qH[jj]);
            }
        }
    } else if (bid < SGRID + 32) {
        // ---------------- X = nW2 @ Wv : 8 rows per block ------------------
        int r = (bid - SGRID) * 8 + w;
        for (int i = l; i < HDIM; i += 32) rows[w][i] = __ldg(nW2 + r * HDIM + i);
        __syncwarp();
        float acc[8] = {0.f, 0.f, 0.f, 0.f, 0.f, 0.f, 0.f, 0.f};
#pragma unroll 4
        for (int k = 0; k < HDIM; k++) {
            float a = rows[w][k];
            const float4* wv = (const float4*)(Wv + k * HDIM);
            float4 v0 = __ldg(wv + l);
            float4 v1 = __ldg(wv + l + 32);
            acc[0] = fmaf(a, v0.x, acc[0]); acc[1] = fmaf(a, v0.y, acc[1]);
            acc[2] = fmaf(a, v0.z, acc[2]); acc[3] = fmaf(a, v0.w, acc[3]);
            acc[4] = fmaf(a, v1.x, acc[4]); acc[5] = fmaf(a, v1.y, acc[5]);
            acc[6] = fmaf(a, v1.z, acc[6]); acc[7] = fmaf(a, v1.w, acc[7]);
        }
        float4* xo = (float4*)(g_X + r * HDIM);
        xo[l]      = make_float4(acc[0], acc[1], acc[2], acc[3]);
        xo[l + 32] = make_float4(acc[4], acc[5], acc[6], acc[7]);
    } else if (bid < SGRID + 64) {
        // ---------------- Y = Wo @ Wp : fold-style, 8 rows per block -------
        const u64* Bv = (const u64*)Wp;
        for (int i = t; i < HDIM * 4; i += 256) Bs[i] = Bv[i];
        __syncthreads();
        int h = (bid - SGRID - 32) * 8 + w;
        const float* Ar = Wo + h * HDIM;
        u64 a0 = 0, a1 = 0, a2 = 0, a3 = 0;
#pragma unroll
        for (int i = 0; i < 8; i++) {
            int k = l + 32 * i;
            float a = __ldg(Ar + k);
            u64 aa = pk(a, a);
            a0 = f2fma(aa, Bs[k * 4 + 0], a0);
            a1 = f2fma(aa, Bs[k * 4 + 1], a1);
            a2 = f2fma(aa, Bs[k * 4 + 2], a2);
            a3 = f2fma(aa, Bs[k * 4 + 3], a3);
        }
        float r[8];
        upk(a0, r[0], r[1]); upk(a1, r[2], r[3]);
        upk(a2, r[4], r[5]); upk(a3, r[6], r[7]);
#pragma unroll
        for (int off = 16; off; off >>= 1)
#pragma unroll
            for (int d = 0; d < 8; d++) r[d] += __shfl_xor_sync(0xffffffffu, r[d], off);
        if (l == 0) {
            float4* o = (float4*)(g_Y + h * 8);
            o[0] = make_float4(r[0], r[1], r[2], r[3]);
            o[1] = make_float4(r[4], r[5], r[6], r[7]);
        }
    } else {
        // ---------------- u = b2 @ Wv : one block, thread per column -------
        float acc = 0.f;
#pragma unroll 8
        for (int k = 0; k < HDIM; k++)
            acc = fmaf(__ldg(b2 + k), __ldg(Wv + k * HDIM + t), acc);
        g_u[t] = acc;
    }
}

// ------------------------- reduce: BN finalize + M/Meff/v row per channel --
__global__ void __launch_bounds__(256) reduce_kernel(const float* __restrict__ gamma,
                                                     const float* __restrict__ beta,
                                                     const float* __restrict__ nf,
                                                     const int* __restrict__ ei0,
                                                     const int* __restrict__ ei1,
                                                     const float* __restrict__ W1,
                                                     const float* __restrict__ b1,
                                                     const float* __restrict__ bv,
                                                     const float* __restrict__ bo,
                                                     const float* __restrict__ Wp,
                                                     int fullE, int E) {
    __shared__ float ss[8], qq[8], Mrow[8];
    __shared__ float sh_scl, sh_shf;
    int h = blockIdx.x, t = threadIdx.x;
    int w = t >> 5, lane = t & 31;

    float2 p0 = g_ps[t * HDIM + h];
    float2 p1 = g_ps[(t + 256) * HDIM + h];
    float s = p0.x + p1.x, q = p0.y + p1.y;
#pragma unroll
    for (int off = 16; off; off >>= 1) {
        s += __shfl_xor_sync(0xffffffffu, s, off);
        q += __shfl_xor_sync(0xffffffffu, q, off);
    }
    if (lane == 0) { ss[w] = s; qq[w] = q; }

    // M[h, d] = X[h,:] @ Y[:, d] : warp d
    {
        float acc = 0.f;
#pragma unroll
        for (int i = 0; i < 8; i++) {
            int k2 = lane + 32 * i;
            acc = fmaf(g_X[h * HDIM + k2], g_Y[k2 * 8 + w], acc);
        }
#pragma unroll
        for (int off = 16; off; off >>= 1) acc += __shfl_xor_sync(0xffffffffu, acc, off);
        if (lane == 0) Mrow[w] = acc;
    }
    __syncthreads();

    if (t == 0) {
        float sv = 0.f, qv = 0.f;
#pragma unroll
        for (int i = 0; i < 8; i++) { sv += ss[i]; qv += qq[i]; }
        for (int e = fullE; e < E; e++) {   // scalar tail (empty when E%16==0)
            int si = __ldg(ei0 + e), ti = __ldg(ei1 + e);
            float z = __ldg(b1 + h);
#pragma unroll
            for (int k = 0; k < 8; k++)
                z = fmaf(0.5f * (__ldg(nf + si * 8 + k) + __ldg(nf + ti * 8 + k)),
                         __ldg(W1 + k * HDIM + h), z);
            float hv = fmaxf(z, 0.f);
            sv += hv; qv = fmaf(hv, hv, qv);
        }
        float invE = 1.0f / (float)E;
        float mu = sv * invE;
        float var = fmaxf(qv * invE - mu * mu, 0.f);
        float scl = gamma[h] * rsqrtf(var + 1e-5f);
        sh_scl = scl;
        sh_shf = beta[h] - mu * scl;
    }
    __syncthreads();

    if (t < 4)
        g_Meff[h * 4 + t] = pk(0.5f * sh_scl * Mrow[2 * t],
                               0.5f * sh_scl * Mrow[2 * t + 1]);
    if (t < DDIM)
        g_v[h * 8 + t] = sh_shf * Mrow[t]
                       + (g_u[h] + __ldg(bv + h)) * g_Y[h * 8 + t]
                       + __ldg(bo + h) * __ldg(Wp + h * 8 + t);
}

// ------------------------- final: c2 = 0.5*(bp + sum_h v[h]) ---------------
__global__ void __launch_bounds__(256) final_kernel(const float* __restrict__ bp) {
    int t = threadIdx.x, w = t >> 5, lane = t & 31;
    if (w < DDIM) {
        float r = 0.f;
#pragma unroll
        for (int i = 0; i < 8; i++) r += g_v[(lane + 32 * i) * 8 + w];
#pragma unroll
        for (int off = 16; off; off >>= 1) r += __shfl_xor_sync(0xffffffffu, r, off);
        if (lane == 0) g_c2[w] = 0.5f * (__ldg(bp + w) + r);
    }
}

// ------------------------- pass B: main (2 edges, LDS.128, bias-seed) ------
__global__ void __launch_bounds__(256, 3) main_kernel(const float* __restrict__ edge_attr,
                                                      const float* __restrict__ nf,
                                                      const int* __restrict__ ei0,
                                                      const int* __restrict__ ei1,
                                                      const float* __restrict__ W1,
                                                      const float* __restrict__ b1,
                                                      float* __restrict__ out,
                                                      int E) {
    __shared__ ulonglong2 wq[HDIM * 2];   // W1eff pairs, 16B rows
    __shared__ ulonglong2 mq[HDIM * 2];   // Meff pairs, 16B rows
    __shared__ u64 b1p[HDIM];             // pk(b1[h], 0)
    int t = threadIdx.x;
    {
        u64* wpu = (u64*)wq;
        u64* mpu = (u64*)mq;
        for (int idx = t; idx < HDIM * 4; idx += 256) {
            int h = idx >> 2, p = idx & 3;
            wpu[idx] = pk(0.5f * W1[(2 * p) * HDIM + h],
                          0.5f * W1[(2 * p + 1) * HDIM + h]);
            mpu[idx] = g_Meff[idx];
        }
        b1p[t] = pk(b1[t], 0.f);
    }
    __syncthreads();

    int base = (blockIdx.x * 256 + t) * 2;
    if (base >= E) return;

    int e0 = base;
    int e1 = min(base + 1, E - 1);

    const float4* nfp = (const float4*)nf;
    u64 nA[4], nB[4];
    {
        int s = __ldg(ei0 + e0), g = __ldg(ei1 + e0);
        float4 a0 = __ldg(nfp + 2 * s), a1 = __ldg(nfp + 2 * s + 1);
        float4 c0 = __ldg(nfp + 2 * g), c1 = __ldg(nfp + 2 * g + 1);
        nA[0] = pk(a0.x + c0.x, a0.y + c0.y);
        nA[1] = pk(a0.z + c0.z, a0.w + c0.w);
        nA[2] = pk(a1.x + c1.x, a1.y + c1.y);
        nA[3] = pk(a1.z + c1.z, a1.w + c1.w);
    }
    {
        int s = __ldg(ei0 + e1), g = __ldg(ei1 + e1);
        float4 a0 = __ldg(nfp + 2 * s), a1 = __ldg(nfp + 2 * s + 1);
        float4 c0 = __ldg(nfp + 2 * g), c1 = __ldg(nfp + 2 * g + 1);
        nB[0] = pk(a0.x + c0.x, a0.y + c0.y);
        nB[1] = pk(a0.z + c0.z, a0.w + c0.w);
        nB[2] = pk(a1.x + c1.x, a1.y + c1.y);
        nB[3] = pk(a1.z + c1.z, a1.w + c1.w);
    }

    u64 aA0 = 0, aA1 = 0, aA2 = 0, aA3 = 0;
    u64 aB0 = 0, aB1 = 0, aB2 = 0, aB3 = 0;

#pragma unroll 2
    for (int h = 0; h < HDIM; h++) {
        ulonglong2 wA = wq[h * 2 + 0], wB = wq[h * 2 + 1];
        ulonglong2 mA = mq[h * 2 + 0], mB = mq[h * 2 + 1];
        u64 bb = b1p[h];

        u64 sA = f2fma(nA[0], wA.x, bb);
        sA = f2fma(nA[1], wA.y, sA);
        sA = f2fma(nA[2], wB.x, sA);
        sA = f2fma(nA[3], wB.y, sA);
        float loA, hiA; upk(sA, loA, hiA);
        float h1A = fmaxf(loA + hiA, 0.f);
        u64 hA = pk(h1A, h1A);
        aA0 = f2fma(hA, mA.x, aA0);
        aA1 = f2fma(hA, mA.y, aA1);
        aA2 = f2fma(hA, mB.x, aA2);
        aA3 = f2fma(hA, mB.y, aA3);

        u64 sB = f2fma(nB[0], wA.x, bb);
        sB = f2fma(nB[1], wA.y, sB);
        sB = f2fma(nB[2], wB.x, sB);
        sB = f2fma(nB[3], wB.y, sB);
        float loB, hiB; upk(sB, loB, hiB);
        float h1B = fmaxf(loB + hiB, 0.f);
        u64 hB = pk(h1B, h1B);
        aB0 = f2fma(hB, mA.x, aB0);
        aB1 = f2fma(hB, mA.y, aB1);
        aB2 = f2fma(hB, mB.x, aB2);
        aB3 = f2fma(hB, mB.y, aB3);
    }

    float cz[8];
#pragma unroll
    for (int d = 0; d < 8; d++) cz[d] = g_c2[d];

    const float4* eap = (const float4*)edge_attr;
    float4* outp = (float4*)out;
    {
        float4 ea0 = __ldg(eap + e0 * 2), ea1 = __ldg(eap + e0 * 2 + 1);
        float x0, x1, x2, x3, x4, x5, x6, x7;
        upk(aA0, x0, x1); upk(aA1, x2, x3);
        upk(aA2, x4, x5); upk(aA3, x6, x7);
        float4 o0, o1;
        o0.x = ea0.x + x0 + cz[0]; o0.y = ea0.y + x1 + cz[1];
        o0.z = ea0.z + x2 + cz[2]; o0.w = ea0.w + x3 + cz[3];
        o1.x = ea1.x + x4 + cz[4]; o1.y = ea1.y + x5 + cz[5];
        o1.z = ea1.z + x6 + cz[6]; o1.w = ea1.w + x7 + cz[7];
        outp[e0 * 2] = o0; outp[e0 * 2 + 1] = o1;
    }
    if (base + 1 < E) {
        float4 ea0 = __ldg(eap + e1 * 2), ea1 = __ldg(eap + e1 * 2 + 1);
        float x0, x1, x2, x3, x4, x5, x6, x7;
        upk(aB0, x0, x1); upk(aB1, x2, x3);
        upk(aB2, x4, x5); upk(aB3, x6, x7);
        float4 o0, o1;
        o0.x = ea0.x + x0 + cz[0]; o0.y = ea0.y + x1 + cz[1];
        o0.z = ea0.z + x2 + cz[2]; o0.w = ea0.w + x3 + cz[3];
        o1.x = ea1.x + x4 + cz[4]; o1.y = ea1.y + x5 + cz[5];
        o1.z = ea1.z + x6 + cz[6]; o1.w = ea1.w + x7 + cz[7];
        outp[e1 * 2] = o0; outp[e1 * 2 + 1] = o1;
    }
}

// ------------------------- launch ------------------------------------------
extern "C" void kernel_launch(void* const* d_in, const int* in_sizes, int n_in,
                              void* d_out, int out_size) {
    const float* edge_attr = (const float*)d_in[0];
    const float* nf        = (const float*)d_in[1];
    const int*   ei        = (const int*)  d_in[2];
    // d_in[3..8] = edge encoder params: dead code in the reference, unused.
    const float* nW1   = (const float*)d_in[9];
    const float* nb1   = (const float*)d_in[10];
    const float* ngam  = (const float*)d_in[11];
    const float* nbet  = (const float*)d_in[12];
    const float* nW2   = (const float*)d_in[13];
    const float* nb2   = (const float*)d_in[14];
    const float* Wv    = (const float*)d_in[15];
    const float* bv    = (const float*)d_in[16];
    const float* Wo    = (const float*)d_in[17];
    const float* bo    = (const float*)d_in[18];
    const float* Wp    = (const float*)d_in[19];
    const float* bp    = (const float*)d_in[20];
    (void)n_in; (void)out_size;

    int E = in_sizes[0] / DDIM;
    const int* ei0 = ei;
    const int* ei1 = ei + E;
    float* out = (float*)d_out;
    int fullE = (E / 16) * 16;

    // stats + X + Y + u in one launch (X/Y/u blocks ride the tail wave)
    mega_kernel<<<SGRID + 65, 256>>>(nf, ei0, ei1, nW1, nb1,
                                     Wo, Wv, nW2, Wp, nb2, fullE);

    // per-channel: BN finalize + M row + Meff pack + c2 contribution
    reduce_kernel<<<HDIM, 256>>>(ngam, nbet, nf, ei0, ei1, nW1, nb1,
                                 bv, bo, Wp, fullE, E);

    // c2 gather (tiny)
    final_kernel<<<1, 256>>>(bp);

    // main fused pass, 2 edges / thread, 3 blocks/SM (no-spill guarantee)
    int gridB = (E + 511) / 512;
    main_kernel<<<gridB, 256>>>(edge_attr, nf, ei0, ei1, nW1, nb1, out, E);
}